// round 10
// baseline (speedup 1.0000x reference)
#include <cuda_runtime.h>
#include <cuda_fp16.h>
#include <stdint.h>

#define NROWS   (64*2048)
#define DIM     64
#define KC      1024
#define QELEMS  (NROWS*DIM)
#define BT      256
#define CKT     128                 // codes per tile
#define NTL     (KC/CKT)            // 8 tiles
#define TBY     (CKT*DIM*2)         // 16 KB per fp16 tile
#define CAP     12

__device__ double  g_loss_acc;
__device__ int     g_ctr;
__device__ int     g_wmax_bits;     // max|w| as float bits (idempotent across replays)
__device__ __half2 g_wh[KC*DIM/2];  // fp16 codebook (128 KB)
__device__ float   g_ssb[KC];       // fp32 code norms (filter-grade)

static __device__ __forceinline__ void cp16(uint32_t dst, const void* src){
    asm volatile("cp.async.cg.shared.global [%0], [%1], 16;" :: "r"(dst), "l"(src));
}

// ---------- prep: convert codebook to fp16, norms, global max|w| ----------
__global__ void vq_prep(const float* __restrict__ w){
    const int gid = blockIdx.x*blockDim.x + threadIdx.x;   // 8192 threads
    float wm = 0.f;
    #pragma unroll
    for (int i=0;i<4;i++){                                  // 4 half2 each
        int k = gid*4 + i;
        float2 v = reinterpret_cast<const float2*>(w)[k];
        g_wh[k] = __floats2half2_rn(v.x, v.y);
        wm = fmaxf(wm, fmaxf(fabsf(v.x), fabsf(v.y)));
    }
    #pragma unroll
    for (int o=16;o>0;o>>=1) wm = fmaxf(wm, __shfl_xor_sync(0xffffffffu, wm, o));
    if ((threadIdx.x & 31) == 0) atomicMax(&g_wmax_bits, __float_as_int(wm));
    if (gid < KC){
        const float4* wr = reinterpret_cast<const float4*>(w + (size_t)gid*DIM);
        float s0=0.f,s1=0.f,s2=0.f,s3=0.f;
        #pragma unroll
        for (int i=0;i<16;i++){
            float4 v = wr[i];
            s0 = __fmaf_rn(v.x,v.x,s0); s1 = __fmaf_rn(v.y,v.y,s1);
            s2 = __fmaf_rn(v.z,v.z,s2); s3 = __fmaf_rn(v.w,v.w,s3);
        }
        g_ssb[gid] = __fadd_rn(__fadd_rn(s0,s1), __fadd_rn(s2,s3));
    }
}

// exact fp32 distance — replicates the round-1 (reference-matching) rounding order
static __device__ __forceinline__ float exact_dist(const float* __restrict__ wrow,
                                                   const float* __restrict__ xv, float cth){
    float ww[64];
    const float4* w4 = reinterpret_cast<const float4*>(wrow);
    #pragma unroll
    for (int i=0;i<16;i++){
        float4 v = w4[i];
        ww[4*i+0]=v.x; ww[4*i+1]=v.y; ww[4*i+2]=v.z; ww[4*i+3]=v.w;
    }
    float ss = 0.f;
    #pragma unroll
    for (int d=0; d<64; d++) ss = __fadd_rn(ss, __fmul_rn(ww[d], ww[d]));
    float s0=0.f, s1=0.f, s2=0.f, s3=0.f;
    #pragma unroll
    for (int d=0; d<64; d+=4){
        s0 = __fmaf_rn(xv[d+0], ww[d+0], s0);
        s1 = __fmaf_rn(xv[d+1], ww[d+1], s1);
        s2 = __fmaf_rn(xv[d+2], ww[d+2], s2);
        s3 = __fmaf_rn(xv[d+3], ww[d+3], s3);
    }
    float m = __fadd_rn(__fadd_rn(s0,s1), __fadd_rn(s2,s3));
    return __fsub_rn(__fadd_rn(cth, ss), __fmul_rn(2.0f, m));
}

__global__ __launch_bounds__(BT, 3) void vq_main(const float* __restrict__ x,
                                                 const float* __restrict__ w,
                                                 float* __restrict__ out)
{
    __shared__ __align__(16) char sB[2][TBY];   // 32 KB fp16 tile double buffer
    __shared__ float  ssv[KC];                  // 4 KB norms
    __shared__ double sred[BT/32];

    const int tid  = threadIdx.x;
    const int lane = tid & 31;
    const int warp = tid >> 5;
    const size_t row = (size_t)blockIdx.x*BT + tid;

    const uint32_t sb0 = (uint32_t)__cvta_generic_to_shared(&sB[0][0]);

    // prologue: tile 0 async + norms to smem
    #pragma unroll
    for (int i=0;i<TBY/(BT*16);i++){
        int G = tid + i*BT;
        cp16(sb0 + G*16, (const char*)g_wh + (size_t)G*16);
    }
    asm volatile("cp.async.commit_group;");
    #pragma unroll
    for (int k=0;k<KC/BT;k++) ssv[tid + k*BT] = g_ssb[tid + k*BT];

    // x row: fp16 regs + exact sequential ||x||^2 + L1 for error bound
    __half2 xh[32];
    float c4 = 0.f, l1x = 0.f;
    {
        const float4* xr = reinterpret_cast<const float4*>(x + row*DIM);
        #pragma unroll
        for (int i=0;i<16;i++){
            float4 v = xr[i];
            c4 = __fadd_rn(c4, __fmul_rn(v.x,v.x));
            c4 = __fadd_rn(c4, __fmul_rn(v.y,v.y));
            c4 = __fadd_rn(c4, __fmul_rn(v.z,v.z));
            c4 = __fadd_rn(c4, __fmul_rn(v.w,v.w));
            l1x += ((fabsf(v.x)+fabsf(v.y))+(fabsf(v.z)+fabsf(v.w)));
            xh[2*i]   = __floats2half2_rn(v.x, v.y);
            xh[2*i+1] = __floats2half2_rn(v.z, v.w);
        }
    }
    const float wmax = __int_as_float(g_wmax_bits);
    const float eb2  = 2.0f * __fmaf_rn(0.02f*wmax, l1x, 1e-4f);  // window width

    float amin = 3.402823466e38f, thresh = 3.402823466e38f;
    int cnt = 0; bool ovf = false;
    unsigned short candI[CAP];
    float          candD[CAP];

    #pragma unroll 1
    for (int t=0; t<NTL; t++){
        if (t+1 < NTL){
            const char* srcb = (const char*)g_wh + (size_t)(t+1)*TBY;
            uint32_t dstb = sb0 + (uint32_t)(((t+1)&1)*TBY);
            #pragma unroll
            for (int i=0;i<TBY/(BT*16);i++){
                int G = tid + i*BT;
                cp16(dstb + G*16, srcb + (size_t)G*16);
            }
            asm volatile("cp.async.commit_group;");
            asm volatile("cp.async.wait_group 1;");
        } else {
            asm volatile("cp.async.wait_group 0;");
        }
        __syncthreads();

        const char* tb = &sB[t&1][0];
        const int cbase = t*CKT;
        #pragma unroll 2
        for (int c=0;c<CKT;c++){
            const uint4* cp = reinterpret_cast<const uint4*>(tb + c*128);
            __half2 a0 = __float2half2_rn(0.f), a1 = a0, a2 = a0, a3 = a0;
            #pragma unroll
            for (int j=0;j<8;j++){
                uint4 ch = cp[j];                       // 16B = 4 half2 (broadcast)
                a0 = __hfma2(xh[4*j+0], *reinterpret_cast<__half2*>(&ch.x), a0);
                a1 = __hfma2(xh[4*j+1], *reinterpret_cast<__half2*>(&ch.y), a1);
                a2 = __hfma2(xh[4*j+2], *reinterpret_cast<__half2*>(&ch.z), a2);
                a3 = __hfma2(xh[4*j+3], *reinterpret_cast<__half2*>(&ch.w), a3);
            }
            __half2 s = __hadd2(__hadd2(a0,a1), __hadd2(a2,a3));
            float dot = __low2float(s) + __high2float(s);
            float dva = __fmaf_rn(dot, -2.0f, c4 + ssv[cbase + c]);
            if (dva <= thresh){
                if (dva < amin){ amin = dva; thresh = amin + eb2; }
                if (cnt == CAP){                       // compact vs current window
                    int m = 0;
                    #pragma unroll
                    for (int t2=0;t2<CAP;t2++){
                        if (candD[t2] <= thresh){
                            candD[m]=candD[t2]; candI[m]=candI[t2]; m++;
                        }
                    }
                    cnt = m;
                }
                if (cnt < CAP){ candI[cnt]=(unsigned short)(cbase+c); candD[cnt]=dva; cnt++; }
                else ovf = true;
            }
        }
        __syncthreads();
    }

    // exact recheck (ascending index, strict <  => first-min)
    float xv[64];
    {
        const float4* xr = reinterpret_cast<const float4*>(x + row*DIM);
        #pragma unroll
        for (int i=0;i<16;i++){
            float4 v = xr[i];
            xv[4*i+0]=v.x; xv[4*i+1]=v.y; xv[4*i+2]=v.z; xv[4*i+3]=v.w;
        }
    }
    float minv = 3.402823466e38f; int mini = 0;
    if (!ovf){
        for (int k=0;k<cnt;k++){
            if (candD[k] <= thresh){
                int idx = (int)candI[k];
                float d = exact_dist(w + (size_t)idx*DIM, xv, c4);
                if (d < minv){ minv = d; mini = idx; }
            }
        }
    } else {   // safety net: full exact scan
        for (int idx=0; idx<KC; idx++){
            float d = exact_dist(w + (size_t)idx*DIM, xv, c4);
            if (d < minv){ minv = d; mini = idx; }
        }
    }

    // outputs
    out[1 + QELEMS + row] = (float)mini;
    {
        const float4* qw = reinterpret_cast<const float4*>(w + (size_t)mini*DIM);
        float stq[64];
        #pragma unroll
        for (int i=0;i<16;i++){
            float4 qv = qw[i];
            stq[4*i+0] = __fadd_rn(xv[4*i+0], __fsub_rn(qv.x, xv[4*i+0]));
            stq[4*i+1] = __fadd_rn(xv[4*i+1], __fsub_rn(qv.y, xv[4*i+1]));
            stq[4*i+2] = __fadd_rn(xv[4*i+2], __fsub_rn(qv.z, xv[4*i+2]));
            stq[4*i+3] = __fadd_rn(xv[4*i+3], __fsub_rn(qv.w, xv[4*i+3]));
        }
        // out+1 is 4B-aligned only: 3 scalars, 15 float4, 1 scalar
        float* og = out + 1 + row*DIM;
        og[0]=stq[0]; og[1]=stq[1]; og[2]=stq[2];
        float4* ov = reinterpret_cast<float4*>(og + 3);
        #pragma unroll
        for (int i=0;i<15;i++){
            float4 r;
            r.x=stq[3+4*i]; r.y=stq[4+4*i]; r.z=stq[5+4*i]; r.w=stq[6+4*i];
            ov[i] = r;
        }
        og[63]=stq[63];
    }

    // fp64 loss reduction + fused finalize
    double vsum = (double)minv;
    #pragma unroll
    for (int o=16;o>0;o>>=1) vsum += __shfl_down_sync(0xffffffffu, vsum, o);
    if (lane == 0) sred[warp] = vsum;
    __syncthreads();
    if (tid == 0){
        double s = 0.0;
        #pragma unroll
        for (int i=0;i<BT/32;i++) s += sred[i];
        atomicAdd(&g_loss_acc, s);
        __threadfence();
        int done = atomicAdd(&g_ctr, 1);
        if (done == (int)gridDim.x - 1){
            double tot = atomicAdd(&g_loss_acc, 0.0);
            out[0] = (float)(tot*1.25/(double)QELEMS);
            g_ctr = 0;
            g_loss_acc = 0.0;
        }
    }
}

extern "C" void kernel_launch(void* const* d_in, const int* in_sizes, int n_in,
                              void* d_out, int out_size)
{
    const float* x  = (const float*)d_in[0];
    const float* wt = (const float*)d_in[1];
    float* out = (float*)d_out;
    vq_prep<<<32, BT>>>(wt);
    vq_main<<<NROWS/BT, BT>>>(x, wt, out);
}

// round 11
// speedup vs baseline: 1.7631x; 1.7631x over previous
#include <cuda_runtime.h>
#include <stdint.h>

#define NROWS   (64*2048)
#define DIM     64
#define KC      1024
#define QELEMS  (NROWS*DIM)
#define BT      256
#define RWS     64                 // rows per CTA
#define CKT     64                 // codes per tile
#define NTL     (KC/CKT)           // 16 tiles
#define TB      (CKT*DIM*4)        // 16 KB per code tile

// dynamic smem offsets (bytes)
#define SM_X    0                   // x tile, k2-major: 16 KB
#define SM_C    16384               // code tiles x2: 32 KB
#define SM_SS   49152               // float ssv[1024]
#define SM_C4   53248               // float c4v[64]
#define SM_RV   53504               // float resV[64]
#define SM_RI   53760               // int resI[64]
#define SM_RED  54016               // double sred[2]
#define SMEMSZ  54144

__device__ double g_loss_acc;
__device__ int    g_ctr;
__device__ float  g_ssb[KC];

static __device__ __forceinline__ unsigned long long ffma2(unsigned long long a,
                                                           unsigned long long b,
                                                           unsigned long long c){
    unsigned long long r;
    asm("fma.rn.f32x2 %0, %1, %2, %3;" : "=l"(r) : "l"(a), "l"(b), "l"(c));
    return r;
}
static __device__ __forceinline__ void unpack2(unsigned long long v, float& a, float& b){
    asm("mov.b64 {%0,%1}, %2;" : "=f"(a), "=f"(b) : "l"(v));
}
static __device__ __forceinline__ unsigned long long lds64(uint32_t a){
    unsigned long long r;
    asm volatile("ld.shared.u64 %0, [%1];" : "=l"(r) : "r"(a));
    return r;
}
static __device__ __forceinline__ void cp8(uint32_t dst, const void* src){
    asm volatile("cp.async.ca.shared.global [%0], [%1], 8;" :: "r"(dst), "l"(src));
}

// prep: exact sequential code norms (reference rounding order), once
__global__ void vq_prep(const float* __restrict__ w){
    int code = blockIdx.x*blockDim.x + threadIdx.x;   // 1024 threads
    const float4* wr = reinterpret_cast<const float4*>(w + (size_t)code*DIM);
    float s = 0.f;
    #pragma unroll
    for (int i=0;i<16;i++){
        float4 v = wr[i];
        s = __fadd_rn(s, __fmul_rn(v.x,v.x));
        s = __fadd_rn(s, __fmul_rn(v.y,v.y));
        s = __fadd_rn(s, __fmul_rn(v.z,v.z));
        s = __fadd_rn(s, __fmul_rn(v.w,v.w));
    }
    g_ssb[code] = s;
}

__global__ __launch_bounds__(BT, 3) void vq_main(const float* __restrict__ x,
                                                 const float* __restrict__ w,
                                                 float* __restrict__ out)
{
    extern __shared__ char sm[];
    float*  ssv  = reinterpret_cast<float*>(sm + SM_SS);
    float*  c4v  = reinterpret_cast<float*>(sm + SM_C4);
    float*  resV = reinterpret_cast<float*>(sm + SM_RV);
    int*    resI = reinterpret_cast<int*>(sm + SM_RI);
    double* sred = reinterpret_cast<double*>(sm + SM_RED);

    const int tid = threadIdx.x;
    const int j   = tid & 15;          // code group 0..15
    const int i   = tid >> 4;          // row group 0..15
    const size_t base = (size_t)blockIdx.x * RWS;

    const uint32_t smb  = (uint32_t)__cvta_generic_to_shared(sm);
    const uint32_t smx  = smb + SM_X;
    const uint32_t smc  = smb + SM_C;

    // ---- async x tile: chunk m = row*32+k2 -> smem [k2][row][8B] ----
    {
        const char* xs = (const char*)x + base*DIM*4;
        #pragma unroll
        for (int q=0;q<8;q++){
            int m = tid + q*BT;
            cp8(smx + (uint32_t)((m&31)*512 + (m>>5)*8), xs + (size_t)m*8);
        }
        asm volatile("cp.async.commit_group;");
    }
    // ---- async code tile 0 ----
    #pragma unroll
    for (int q=0;q<8;q++){
        int m = tid + q*BT;
        cp8(smc + (uint32_t)((m&31)*512 + (m>>5)*8), (const char*)w + (size_t)m*8);
    }
    asm volatile("cp.async.commit_group;");

    // ---- norms to smem ----
    #pragma unroll
    for (int k=0;k<KC/BT;k++) ssv[tid + k*BT] = g_ssb[tid + k*BT];
    if (tid < RWS){
        const float4* xr = reinterpret_cast<const float4*>(x + (base + tid)*DIM);
        float s = 0.f;
        #pragma unroll
        for (int q=0;q<16;q++){
            float4 v = xr[q];
            s = __fadd_rn(s, __fmul_rn(v.x,v.x));
            s = __fadd_rn(s, __fmul_rn(v.y,v.y));
            s = __fadd_rn(s, __fmul_rn(v.z,v.z));
            s = __fadd_rn(s, __fmul_rn(v.w,v.w));
        }
        c4v[tid] = s;
    }

    float minv[4] = {3.4e38f,3.4e38f,3.4e38f,3.4e38f};
    int   mini[4] = {0,0,0,0};
    float c4r[4];

    const uint32_t xb = smx + (uint32_t)(i*8);
    bool c4ld = false;

    #pragma unroll 1
    for (int t=0; t<NTL; t++){
        if (t+1 < NTL){
            const char* srcb = (const char*)w + (size_t)(t+1)*TB;
            uint32_t dstb = smc + (uint32_t)(((t+1)&1)*TB);
            #pragma unroll
            for (int q=0;q<8;q++){
                int m = tid + q*BT;
                cp8(dstb + (uint32_t)((m&31)*512 + (m>>5)*8), srcb + (size_t)m*8);
            }
            asm volatile("cp.async.commit_group;");
            asm volatile("cp.async.wait_group 1;");
        } else {
            asm volatile("cp.async.wait_group 0;");
        }
        __syncthreads();
        if (!c4ld){      // first iter: c4v/ssv now visible
            c4ld = true;
            #pragma unroll
            for (int s=0;s<4;s++) c4r[s] = c4v[i + 16*s];
        }

        const uint32_t cb = smc + (uint32_t)((t&1)*TB) + (uint32_t)(j*8);
        unsigned long long acc[16];
        #pragma unroll
        for (int q=0;q<16;q++) acc[q] = 0ull;

        #pragma unroll 4
        for (int k2=0;k2<32;k2++){
            uint32_t xa = xb + (uint32_t)(k2*512);
            uint32_t ca = cb + (uint32_t)(k2*512);
            unsigned long long rf0 = lds64(xa);
            unsigned long long rf1 = lds64(xa + 128);
            unsigned long long rf2 = lds64(xa + 256);
            unsigned long long rf3 = lds64(xa + 384);
            unsigned long long cf0 = lds64(ca);
            unsigned long long cf1 = lds64(ca + 128);
            unsigned long long cf2 = lds64(ca + 256);
            unsigned long long cf3 = lds64(ca + 384);
            acc[0]  = ffma2(rf0, cf0, acc[0]);
            acc[1]  = ffma2(rf0, cf1, acc[1]);
            acc[2]  = ffma2(rf0, cf2, acc[2]);
            acc[3]  = ffma2(rf0, cf3, acc[3]);
            acc[4]  = ffma2(rf1, cf0, acc[4]);
            acc[5]  = ffma2(rf1, cf1, acc[5]);
            acc[6]  = ffma2(rf1, cf2, acc[6]);
            acc[7]  = ffma2(rf1, cf3, acc[7]);
            acc[8]  = ffma2(rf2, cf0, acc[8]);
            acc[9]  = ffma2(rf2, cf1, acc[9]);
            acc[10] = ffma2(rf2, cf2, acc[10]);
            acc[11] = ffma2(rf2, cf3, acc[11]);
            acc[12] = ffma2(rf3, cf0, acc[12]);
            acc[13] = ffma2(rf3, cf1, acc[13]);
            acc[14] = ffma2(rf3, cf2, acc[14]);
            acc[15] = ffma2(rf3, cf3, acc[15]);
        }

        // tail: 16 dots; codes ascend in r for first-min semantics
        float ssq[4];
        #pragma unroll
        for (int r=0;r<4;r++) ssq[r] = ssv[t*CKT + 16*r + j];
        #pragma unroll
        for (int s=0;s<4;s++){
            #pragma unroll
            for (int r=0;r<4;r++){
                float lo, hi;
                unpack2(acc[s*4+r], lo, hi);
                float m  = __fadd_rn(lo, hi);
                float dv = __fmaf_rn(m, -2.0f, __fadd_rn(c4r[s], ssq[r]));
                int  idx = t*CKT + 16*r + j;
                if (dv < minv[s]){ minv[s] = dv; mini[s] = idx; }
            }
        }
        __syncthreads();
    }

    // ---- cross-j reduce (16-lane groups), lexicographic (dv, idx) ----
    #pragma unroll
    for (int off=1; off<16; off<<=1){
        #pragma unroll
        for (int s=0;s<4;s++){
            float od = __shfl_xor_sync(0xffffffffu, minv[s], off);
            int   oi = __shfl_xor_sync(0xffffffffu, mini[s], off);
            if (od < minv[s] || (od == minv[s] && oi < mini[s])){
                minv[s] = od; mini[s] = oi;
            }
        }
    }
    if (j == 0){
        #pragma unroll
        for (int s=0;s<4;s++){ resV[i + 16*s] = minv[s]; resI[i + 16*s] = mini[s]; }
    }
    __syncthreads();

    // ---- loss partial (warps 0,1 cover rows 0..63) ----
    if (tid < RWS){
        double v = (double)resV[tid];
        #pragma unroll
        for (int o=16;o>0;o>>=1) v += __shfl_down_sync(0xffffffffu, v, o);
        if ((tid & 31) == 0) sred[tid>>5] = v;
    }
    __syncthreads();
    if (tid == 0){
        atomicAdd(&g_loss_acc, sred[0] + sred[1]);
        __threadfence();
        int done = atomicAdd(&g_ctr, 1);
        if (done == (int)gridDim.x - 1){
            double tot = atomicAdd(&g_loss_acc, 0.0);
            out[0] = (float)(tot*1.25/(double)QELEMS);
            g_ctr = 0;
            g_loss_acc = 0.0;
        }
    }

    // ---- epilogue: indices + straight-through rows (4 threads/row) ----
    {
        int rloc = tid >> 2;                 // row 0..63
        int c    = tid & 3;                  // 16-dim chunk
        size_t grow = base + rloc;
        int idx = resI[rloc];
        if (c == 0) out[1 + QELEMS + grow] = (float)idx;

        const float4* qw = reinterpret_cast<const float4*>(w + (size_t)idx*DIM + c*16);
        const float4* xr = reinterpret_cast<const float4*>(x + grow*DIM + c*16);
        float stq[16];
        #pragma unroll
        for (int q=0;q<4;q++){
            float4 qv = qw[q];
            float4 xv = xr[q];
            stq[4*q+0] = __fadd_rn(xv.x, __fsub_rn(qv.x, xv.x));
            stq[4*q+1] = __fadd_rn(xv.y, __fsub_rn(qv.y, xv.y));
            stq[4*q+2] = __fadd_rn(xv.z, __fsub_rn(qv.z, xv.z));
            stq[4*q+3] = __fadd_rn(xv.w, __fsub_rn(qv.w, xv.w));
        }
        // out+1 is 4B-aligned: (1 + 16c) % 4 == 1 -> 3 scalars, 3 float4, 1 scalar
        float* og = out + 1 + grow*DIM + c*16;
        og[0]=stq[0]; og[1]=stq[1]; og[2]=stq[2];
        float4* ov = reinterpret_cast<float4*>(og + 3);
        #pragma unroll
        for (int q=0;q<3;q++){
            float4 r;
            r.x=stq[3+4*q]; r.y=stq[4+4*q]; r.z=stq[5+4*q]; r.w=stq[6+4*q];
            ov[q] = r;
        }
        og[15]=stq[15];
    }
}

extern "C" void kernel_launch(void* const* d_in, const int* in_sizes, int n_in,
                              void* d_out, int out_size)
{
    const float* x  = (const float*)d_in[0];
    const float* wt = (const float*)d_in[1];
    float* out = (float*)d_out;

    cudaFuncSetAttribute(vq_main, cudaFuncAttributeMaxDynamicSharedMemorySize, SMEMSZ);

    vq_prep<<<KC/BT, BT>>>(wt);
    vq_main<<<NROWS/RWS, BT, SMEMSZ>>>(x, wt, out);
}

// round 12
// speedup vs baseline: 2.2097x; 1.2533x over previous
#include <cuda_runtime.h>
#include <stdint.h>

#define NROWS   (64*2048)
#define DIM     64
#define KC      1024
#define QELEMS  (NROWS*DIM)
#define BT      256
#define RWS     64                 // rows per CTA
#define CKT     64                 // codes per tile
#define NTL     (KC/CKT)           // 16 tiles
#define TB      (CKT*DIM*4)        // 16 KB per code tile

// dynamic smem offsets (bytes)
#define SM_X    0                   // x tile [k2p][row][16B]: 16 KB
#define SM_C    16384               // code tiles x2 [k2p][code][16B]: 32 KB
#define SM_SS   49152               // float ssv[1024]
#define SM_C4   53248               // float c4v[64]
#define SM_RV   53504               // float resV[64]
#define SM_RI   53760               // int resI[64]
#define SM_RED  54016               // double sred[2]
#define SMEMSZ  54144

__device__ double g_loss_acc;
__device__ int    g_ctr;
__device__ float  g_ssb[KC];

static __device__ __forceinline__ unsigned long long ffma2(unsigned long long a,
                                                           unsigned long long b,
                                                           unsigned long long c){
    unsigned long long r;
    asm("fma.rn.f32x2 %0, %1, %2, %3;" : "=l"(r) : "l"(a), "l"(b), "l"(c));
    return r;
}
static __device__ __forceinline__ void unpack2(unsigned long long v, float& a, float& b){
    asm("mov.b64 {%0,%1}, %2;" : "=f"(a), "=f"(b) : "l"(v));
}
static __device__ __forceinline__ void lds128(uint32_t a, unsigned long long& u,
                                              unsigned long long& v){
    asm volatile("ld.shared.v2.u64 {%0,%1}, [%2];" : "=l"(u), "=l"(v) : "r"(a));
}
static __device__ __forceinline__ void cp16(uint32_t dst, const void* src){
    asm volatile("cp.async.cg.shared.global [%0], [%1], 16;" :: "r"(dst), "l"(src));
}

// prep: exact sequential code norms (reference rounding order), once
__global__ void vq_prep(const float* __restrict__ w){
    int code = blockIdx.x*blockDim.x + threadIdx.x;   // 1024 threads
    const float4* wr = reinterpret_cast<const float4*>(w + (size_t)code*DIM);
    float s = 0.f;
    #pragma unroll
    for (int i=0;i<16;i++){
        float4 v = wr[i];
        s = __fadd_rn(s, __fmul_rn(v.x,v.x));
        s = __fadd_rn(s, __fmul_rn(v.y,v.y));
        s = __fadd_rn(s, __fmul_rn(v.z,v.z));
        s = __fadd_rn(s, __fmul_rn(v.w,v.w));
    }
    g_ssb[code] = s;
}

__global__ __launch_bounds__(BT, 3) void vq_main(const float* __restrict__ x,
                                                 const float* __restrict__ w,
                                                 float* __restrict__ out)
{
    extern __shared__ char sm[];
    float*  ssv  = reinterpret_cast<float*>(sm + SM_SS);
    float*  c4v  = reinterpret_cast<float*>(sm + SM_C4);
    float*  resV = reinterpret_cast<float*>(sm + SM_RV);
    int*    resI = reinterpret_cast<int*>(sm + SM_RI);
    double* sred = reinterpret_cast<double*>(sm + SM_RED);

    const int tid = threadIdx.x;
    const int j   = tid & 15;          // code group 0..15
    const int i   = tid >> 4;          // row group 0..15
    const size_t base = (size_t)blockIdx.x * RWS;

    const uint32_t smb = (uint32_t)__cvta_generic_to_shared(sm);
    const uint32_t smx = smb + SM_X;
    const uint32_t smc = smb + SM_C;

    // ---- async x tile: chunk m -> (r=m&63, g=m>>6); dst [g][r][16B] ----
    {
        const char* xs = (const char*)x + base*DIM*4;
        #pragma unroll
        for (int q=0;q<4;q++){
            int m = tid + q*BT;
            int r = m & 63, g = m >> 6;
            cp16(smx + (uint32_t)(g*1024 + r*16), xs + (size_t)r*256 + g*16);
        }
        asm volatile("cp.async.commit_group;");
    }
    // ---- async code tile 0 ----
    #pragma unroll
    for (int q=0;q<4;q++){
        int m = tid + q*BT;
        int c = m & 63, g = m >> 6;
        cp16(smc + (uint32_t)(g*1024 + c*16), (const char*)w + (size_t)c*256 + g*16);
    }
    asm volatile("cp.async.commit_group;");

    // ---- norms to smem ----
    #pragma unroll
    for (int k=0;k<KC/BT;k++) ssv[tid + k*BT] = g_ssb[tid + k*BT];
    if (tid < RWS){
        const float4* xr = reinterpret_cast<const float4*>(x + (base + tid)*DIM);
        float s = 0.f;
        #pragma unroll
        for (int q=0;q<16;q++){
            float4 v = xr[q];
            s = __fadd_rn(s, __fmul_rn(v.x,v.x));
            s = __fadd_rn(s, __fmul_rn(v.y,v.y));
            s = __fadd_rn(s, __fmul_rn(v.z,v.z));
            s = __fadd_rn(s, __fmul_rn(v.w,v.w));
        }
        c4v[tid] = s;
    }

    float minv[4] = {3.4e38f,3.4e38f,3.4e38f,3.4e38f};
    int   mini[4] = {0,0,0,0};
    float c4r[4];

    const uint32_t xb = smx + (uint32_t)(i*16);
    bool c4ld = false;

    #pragma unroll 1
    for (int t=0; t<NTL; t++){
        if (t+1 < NTL){
            const char* srcb = (const char*)w + (size_t)(t+1)*TB;
            uint32_t dstb = smc + (uint32_t)(((t+1)&1)*TB);
            #pragma unroll
            for (int q=0;q<4;q++){
                int m = tid + q*BT;
                int c = m & 63, g = m >> 6;
                cp16(dstb + (uint32_t)(g*1024 + c*16), srcb + (size_t)c*256 + g*16);
            }
            asm volatile("cp.async.commit_group;");
            asm volatile("cp.async.wait_group 1;");
        } else {
            asm volatile("cp.async.wait_group 0;");
        }
        __syncthreads();
        if (!c4ld){
            c4ld = true;
            #pragma unroll
            for (int s=0;s<4;s++) c4r[s] = c4v[i + 16*s];
        }

        const uint32_t cb = smc + (uint32_t)((t&1)*TB) + (uint32_t)(j*16);
        unsigned long long acc[16];
        #pragma unroll
        for (int q=0;q<16;q++) acc[q] = 0ull;

        #pragma unroll 4
        for (int p=0;p<16;p++){                 // k2-pair: dims 4p..4p+3
            uint32_t xa = xb + (uint32_t)(p*1024);
            uint32_t ca = cb + (uint32_t)(p*1024);
            unsigned long long rA[4][2], cA[4][2];
            lds128(xa,       rA[0][0], rA[0][1]);
            lds128(xa + 256, rA[1][0], rA[1][1]);
            lds128(xa + 512, rA[2][0], rA[2][1]);
            lds128(xa + 768, rA[3][0], rA[3][1]);
            lds128(ca,       cA[0][0], cA[0][1]);
            lds128(ca + 256, cA[1][0], cA[1][1]);
            lds128(ca + 512, cA[2][0], cA[2][1]);
            lds128(ca + 768, cA[3][0], cA[3][1]);
            #pragma unroll
            for (int s=0;s<4;s++){
                #pragma unroll
                for (int r=0;r<4;r++){
                    acc[s*4+r] = ffma2(rA[s][0], cA[r][0], acc[s*4+r]);
                    acc[s*4+r] = ffma2(rA[s][1], cA[r][1], acc[s*4+r]);
                }
            }
        }

        // tail: 16 dots; codes ascend in r for first-min semantics
        float ssq[4];
        #pragma unroll
        for (int r=0;r<4;r++) ssq[r] = ssv[t*CKT + 16*r + j];
        #pragma unroll
        for (int s=0;s<4;s++){
            #pragma unroll
            for (int r=0;r<4;r++){
                float lo, hi;
                unpack2(acc[s*4+r], lo, hi);
                float m  = __fadd_rn(lo, hi);
                float dv = __fmaf_rn(m, -2.0f, __fadd_rn(c4r[s], ssq[r]));
                int  idx = t*CKT + 16*r + j;
                if (dv < minv[s]){ minv[s] = dv; mini[s] = idx; }
            }
        }
        __syncthreads();
    }

    // ---- cross-j reduce (16-lane groups), lexicographic (dv, idx) ----
    #pragma unroll
    for (int off=1; off<16; off<<=1){
        #pragma unroll
        for (int s=0;s<4;s++){
            float od = __shfl_xor_sync(0xffffffffu, minv[s], off);
            int   oi = __shfl_xor_sync(0xffffffffu, mini[s], off);
            if (od < minv[s] || (od == minv[s] && oi < mini[s])){
                minv[s] = od; mini[s] = oi;
            }
        }
    }
    if (j == 0){
        #pragma unroll
        for (int s=0;s<4;s++){ resV[i + 16*s] = minv[s]; resI[i + 16*s] = mini[s]; }
    }
    __syncthreads();

    // ---- loss partial (rows 0..63 by first 64 threads) ----
    if (tid < RWS){
        double v = (double)resV[tid];
        #pragma unroll
        for (int o=16;o>0;o>>=1) v += __shfl_down_sync(0xffffffffu, v, o);
        if ((tid & 31) == 0) sred[tid>>5] = v;
    }
    __syncthreads();
    if (tid == 0){
        atomicAdd(&g_loss_acc, sred[0] + sred[1]);
        __threadfence();
        int done = atomicAdd(&g_ctr, 1);
        if (done == (int)gridDim.x - 1){
            double tot = atomicAdd(&g_loss_acc, 0.0);
            out[0] = (float)(tot*1.25/(double)QELEMS);
            g_ctr = 0;
            g_loss_acc = 0.0;
        }
    }

    // ---- epilogue: indices + straight-through rows (4 threads/row) ----
    {
        int rloc = tid >> 2;                 // row 0..63
        int c    = tid & 3;                  // 16-dim chunk
        size_t grow = base + rloc;
        int idx = resI[rloc];
        if (c == 0) out[1 + QELEMS + grow] = (float)idx;

        const float4* qw = reinterpret_cast<const float4*>(w + (size_t)idx*DIM + c*16);
        const float4* xr = reinterpret_cast<const float4*>(x + grow*DIM + c*16);
        float stq[16];
        #pragma unroll
        for (int q=0;q<4;q++){
            float4 qv = qw[q];
            float4 xv = xr[q];
            stq[4*q+0] = __fadd_rn(xv.x, __fsub_rn(qv.x, xv.x));
            stq[4*q+1] = __fadd_rn(xv.y, __fsub_rn(qv.y, xv.y));
            stq[4*q+2] = __fadd_rn(xv.z, __fsub_rn(qv.z, xv.z));
            stq[4*q+3] = __fadd_rn(xv.w, __fsub_rn(qv.w, xv.w));
        }
        // out+1 is 4B-aligned: 3 scalars, 3 float4, 1 scalar per 16-chunk
        float* og = out + 1 + grow*DIM + c*16;
        og[0]=stq[0]; og[1]=stq[1]; og[2]=stq[2];
        float4* ov = reinterpret_cast<float4*>(og + 3);
        #pragma unroll
        for (int q=0;q<3;q++){
            float4 r;
            r.x=stq[3+4*q]; r.y=stq[4+4*q]; r.z=stq[5+4*q]; r.w=stq[6+4*q];
            ov[q] = r;
        }
        og[15]=stq[15];
    }
}

extern "C" void kernel_launch(void* const* d_in, const int* in_sizes, int n_in,
                              void* d_out, int out_size)
{
    const float* x  = (const float*)d_in[0];
    const float* wt = (const float*)d_in[1];
    float* out = (float*)d_out;

    cudaFuncSetAttribute(vq_main, cudaFuncAttributeMaxDynamicSharedMemorySize, SMEMSZ);

    vq_prep<<<KC/BT, BT>>>(wt);
    vq_main<<<NROWS/RWS, BT, SMEMSZ>>>(x, wt, out);
}

// round 13
// speedup vs baseline: 2.3297x; 1.0543x over previous
#include <cuda_runtime.h>
#include <stdint.h>

#define NROWS   (64*2048)
#define DIM     64
#define KC      1024
#define QELEMS  (NROWS*DIM)
#define BT      256
#define RWS     64                 // rows per CTA
#define CKT     64                 // codes per tile
#define NTL     (KC/CKT)           // 16 tiles
#define TB      (CKT*DIM*4)        // 16 KB per code tile

// dynamic smem offsets (bytes)
#define SM_X    0                   // x tile [k2p][row][16B]: 16 KB
#define SM_C    16384               // code tiles x2 [k2p][code][16B]: 32 KB
#define SM_SS   49152               // float ssv[1024]
#define SM_C4   53248               // float c4v[64]
#define SM_RV   53504               // float resV[64]
#define SM_RI   53760               // int resI[64]
#define SM_RED  54016               // double sred[2]
#define SMEMSZ  54144

__device__ double g_loss_acc;
__device__ int    g_ctr;
__device__ float  g_ssb[KC];

static __device__ __forceinline__ unsigned long long ffma2(unsigned long long a,
                                                           unsigned long long b,
                                                           unsigned long long c){
    unsigned long long r;
    asm("fma.rn.f32x2 %0, %1, %2, %3;" : "=l"(r) : "l"(a), "l"(b), "l"(c));
    return r;
}
static __device__ __forceinline__ void unpack2(unsigned long long v, float& a, float& b){
    asm("mov.b64 {%0,%1}, %2;" : "=f"(a), "=f"(b) : "l"(v));
}
static __device__ __forceinline__ void cp16(uint32_t dst, const void* src){
    asm volatile("cp.async.cg.shared.global [%0], [%1], 16;" :: "r"(dst), "l"(src));
}

// prep: exact sequential code norms (reference rounding order), once
__global__ void vq_prep(const float* __restrict__ w){
    int code = blockIdx.x*blockDim.x + threadIdx.x;   // 1024 threads
    const float4* wr = reinterpret_cast<const float4*>(w + (size_t)code*DIM);
    float s = 0.f;
    #pragma unroll
    for (int i=0;i<16;i++){
        float4 v = wr[i];
        s = __fadd_rn(s, __fmul_rn(v.x,v.x));
        s = __fadd_rn(s, __fmul_rn(v.y,v.y));
        s = __fadd_rn(s, __fmul_rn(v.z,v.z));
        s = __fadd_rn(s, __fmul_rn(v.w,v.w));
    }
    g_ssb[code] = s;
}

__global__ __launch_bounds__(BT, 3) void vq_main(const float* __restrict__ x,
                                                 const float* __restrict__ w,
                                                 float* __restrict__ out)
{
    extern __shared__ char sm[];
    float*  ssv  = reinterpret_cast<float*>(sm + SM_SS);
    float*  c4v  = reinterpret_cast<float*>(sm + SM_C4);
    float*  resV = reinterpret_cast<float*>(sm + SM_RV);
    int*    resI = reinterpret_cast<int*>(sm + SM_RI);
    double* sred = reinterpret_cast<double*>(sm + SM_RED);
    const ulonglong2* XS = reinterpret_cast<const ulonglong2*>(sm + SM_X);
    const ulonglong2* CS = reinterpret_cast<const ulonglong2*>(sm + SM_C);

    const int tid = threadIdx.x;
    const int j   = tid & 15;          // code group 0..15
    const int i   = tid >> 4;          // row group 0..15
    const size_t base = (size_t)blockIdx.x * RWS;

    const uint32_t smb = (uint32_t)__cvta_generic_to_shared(sm);
    const uint32_t smx = smb + SM_X;
    const uint32_t smc = smb + SM_C;

    // ---- async x tile: chunk m -> (r=m&63, g=m>>6); dst [g][r][16B] ----
    {
        const char* xs = (const char*)x + base*DIM*4;
        #pragma unroll
        for (int q=0;q<4;q++){
            int m = tid + q*BT;
            int r = m & 63, g = m >> 6;
            cp16(smx + (uint32_t)(g*1024 + r*16), xs + (size_t)r*256 + g*16);
        }
        asm volatile("cp.async.commit_group;");
    }
    // ---- async code tile 0 ----
    #pragma unroll
    for (int q=0;q<4;q++){
        int m = tid + q*BT;
        int c = m & 63, g = m >> 6;
        cp16(smc + (uint32_t)(g*1024 + c*16), (const char*)w + (size_t)c*256 + g*16);
    }
    asm volatile("cp.async.commit_group;");

    // ---- norms to smem ----
    #pragma unroll
    for (int k=0;k<KC/BT;k++) ssv[tid + k*BT] = g_ssb[tid + k*BT];
    if (tid < RWS){
        const float4* xr = reinterpret_cast<const float4*>(x + (base + tid)*DIM);
        float s = 0.f;
        #pragma unroll
        for (int q=0;q<16;q++){
            float4 v = xr[q];
            s = __fadd_rn(s, __fmul_rn(v.x,v.x));
            s = __fadd_rn(s, __fmul_rn(v.y,v.y));
            s = __fadd_rn(s, __fmul_rn(v.z,v.z));
            s = __fadd_rn(s, __fmul_rn(v.w,v.w));
        }
        c4v[tid] = s;
    }

    float minv[4] = {3.4e38f,3.4e38f,3.4e38f,3.4e38f};
    int   mini[4] = {0,0,0,0};
    float c4r[4];
    bool c4ld = false;

    #pragma unroll 1
    for (int t=0; t<NTL; t++){
        if (t+1 < NTL){
            const char* srcb = (const char*)w + (size_t)(t+1)*TB;
            uint32_t dstb = smc + (uint32_t)(((t+1)&1)*TB);
            #pragma unroll
            for (int q=0;q<4;q++){
                int m = tid + q*BT;
                int c = m & 63, g = m >> 6;
                cp16(dstb + (uint32_t)(g*1024 + c*16), srcb + (size_t)c*256 + g*16);
            }
            asm volatile("cp.async.commit_group;");
            asm volatile("cp.async.wait_group 1;");
        } else {
            asm volatile("cp.async.wait_group 0;");
        }
        __syncthreads();
        if (!c4ld){
            c4ld = true;
            #pragma unroll
            for (int s=0;s<4;s++) c4r[s] = c4v[i + 16*s];
        }

        const ulonglong2* Ct = CS + (t&1)*(TB/16);
        unsigned long long acc[16];
        #pragma unroll
        for (int q=0;q<16;q++) acc[q] = 0ull;

        #pragma unroll 4
        for (int p=0;p<16;p++){                 // k2-pair: dims 4p..4p+3
            ulonglong2 rA[4], cA[4];
            #pragma unroll
            for (int s=0;s<4;s++) rA[s] = XS[p*64 + i + 16*s];
            #pragma unroll
            for (int r=0;r<4;r++) cA[r] = Ct[p*64 + j + 16*r];
            #pragma unroll
            for (int s=0;s<4;s++){
                #pragma unroll
                for (int r=0;r<4;r++){
                    acc[s*4+r] = ffma2(rA[s].x, cA[r].x, acc[s*4+r]);
                    acc[s*4+r] = ffma2(rA[s].y, cA[r].y, acc[s*4+r]);
                }
            }
        }

        // tail: 16 dots; codes ascend in r for first-min semantics
        float ssq[4];
        #pragma unroll
        for (int r=0;r<4;r++) ssq[r] = ssv[t*CKT + 16*r + j];
        #pragma unroll
        for (int s=0;s<4;s++){
            #pragma unroll
            for (int r=0;r<4;r++){
                float lo, hi;
                unpack2(acc[s*4+r], lo, hi);
                float m  = __fadd_rn(lo, hi);
                float dv = __fmaf_rn(m, -2.0f, __fadd_rn(c4r[s], ssq[r]));
                int  idx = t*CKT + 16*r + j;
                if (dv < minv[s]){ minv[s] = dv; mini[s] = idx; }
            }
        }
        __syncthreads();
    }

    // ---- cross-j reduce (16-lane groups), lexicographic (dv, idx) ----
    #pragma unroll
    for (int off=1; off<16; off<<=1){
        #pragma unroll
        for (int s=0;s<4;s++){
            float od = __shfl_xor_sync(0xffffffffu, minv[s], off);
            int   oi = __shfl_xor_sync(0xffffffffu, mini[s], off);
            if (od < minv[s] || (od == minv[s] && oi < mini[s])){
                minv[s] = od; mini[s] = oi;
            }
        }
    }
    if (j == 0){
        #pragma unroll
        for (int s=0;s<4;s++){ resV[i + 16*s] = minv[s]; resI[i + 16*s] = mini[s]; }
    }
    __syncthreads();

    // ---- loss partial (rows 0..63 by first 64 threads) ----
    if (tid < RWS){
        double v = (double)resV[tid];
        #pragma unroll
        for (int o=16;o>0;o>>=1) v += __shfl_down_sync(0xffffffffu, v, o);
        if ((tid & 31) == 0) sred[tid>>5] = v;
    }
    __syncthreads();
    if (tid == 0){
        atomicAdd(&g_loss_acc, sred[0] + sred[1]);
        __threadfence();
        int done = atomicAdd(&g_ctr, 1);
        if (done == (int)gridDim.x - 1){
            double tot = atomicAdd(&g_loss_acc, 0.0);
            out[0] = (float)(tot*1.25/(double)QELEMS);
            g_ctr = 0;
            g_loss_acc = 0.0;
        }
    }

    // ---- epilogue: indices + straight-through rows (4 threads/row) ----
    {
        int rloc = tid >> 2;                 // row 0..63
        int c    = tid & 3;                  // 16-dim chunk
        size_t grow = base + rloc;
        int idx = resI[rloc];
        if (c == 0) out[1 + QELEMS + grow] = (float)idx;

        const float4* qw = reinterpret_cast<const float4*>(w + (size_t)idx*DIM + c*16);
        const float4* xr = reinterpret_cast<const float4*>(x + grow*DIM + c*16);
        float stq[16];
        #pragma unroll
        for (int q=0;q<4;q++){
            float4 qv = qw[q];
            float4 xv = xr[q];
            stq[4*q+0] = __fadd_rn(xv.x, __fsub_rn(qv.x, xv.x));
            stq[4*q+1] = __fadd_rn(xv.y, __fsub_rn(qv.y, xv.y));
            stq[4*q+2] = __fadd_rn(xv.z, __fsub_rn(qv.z, xv.z));
            stq[4*q+3] = __fadd_rn(xv.w, __fsub_rn(qv.w, xv.w));
        }
        // out+1 is 4B-aligned: 3 scalars, 3 float4, 1 scalar per 16-chunk
        float* og = out + 1 + grow*DIM + c*16;
        og[0]=stq[0]; og[1]=stq[1]; og[2]=stq[2];
        float4* ov = reinterpret_cast<float4*>(og + 3);
        #pragma unroll
        for (int q=0;q<3;q++){
            float4 r;
            r.x=stq[3+4*q]; r.y=stq[4+4*q]; r.z=stq[5+4*q]; r.w=stq[6+4*q];
            ov[q] = r;
        }
        og[15]=stq[15];
    }
}

extern "C" void kernel_launch(void* const* d_in, const int* in_sizes, int n_in,
                              void* d_out, int out_size)
{
    const float* x  = (const float*)d_in[0];
    const float* wt = (const float*)d_in[1];
    float* out = (float*)d_out;

    cudaFuncSetAttribute(vq_main, cudaFuncAttributeMaxDynamicSharedMemorySize, SMEMSZ);

    vq_prep<<<KC/BT, BT>>>(wt);
    vq_main<<<NROWS/RWS, BT, SMEMSZ>>>(x, wt, out);
}

// round 14
// speedup vs baseline: 2.5436x; 1.0918x over previous
#include <cuda_runtime.h>
#include <stdint.h>

#define NROWS   (64*2048)
#define DIM     64
#define KC      1024
#define QELEMS  (NROWS*DIM)
#define BT      256
#define RWS     128                // rows per CTA
#define CKT     64                 // codes per tile
#define NTL     (KC/CKT)           // 16 tiles
#define TB      (CKT*DIM*4)        // 16 KB per code tile

// dynamic smem offsets (bytes)
#define SM_X    0                   // x tile [k2p][row][16B]: 32 KB
#define SM_C    32768               // code tiles x2 [k2p][code][16B]: 32 KB
#define SM_SS   65536               // float ssv[1024]
#define SM_C4   69632               // float c4v[128]
#define SM_RV   70144               // float resV[128]
#define SM_RI   70656               // int resI[128]
#define SM_RED  71168               // double sred[4]
#define SMEMSZ  71232

__device__ double g_loss_acc;
__device__ int    g_ctr;
__device__ float  g_ssb[KC];

static __device__ __forceinline__ unsigned long long ffma2(unsigned long long a,
                                                           unsigned long long b,
                                                           unsigned long long c){
    unsigned long long r;
    asm("fma.rn.f32x2 %0, %1, %2, %3;" : "=l"(r) : "l"(a), "l"(b), "l"(c));
    return r;
}
static __device__ __forceinline__ void unpack2(unsigned long long v, float& a, float& b){
    asm("mov.b64 {%0,%1}, %2;" : "=f"(a), "=f"(b) : "l"(v));
}
static __device__ __forceinline__ void cp16(uint32_t dst, const void* src){
    asm volatile("cp.async.cg.shared.global [%0], [%1], 16;" :: "r"(dst), "l"(src));
}

// prep: exact sequential code norms (reference rounding order), once
__global__ void vq_prep(const float* __restrict__ w){
    int code = blockIdx.x*blockDim.x + threadIdx.x;   // 1024 threads
    const float4* wr = reinterpret_cast<const float4*>(w + (size_t)code*DIM);
    float s = 0.f;
    #pragma unroll
    for (int i=0;i<16;i++){
        float4 v = wr[i];
        s = __fadd_rn(s, __fmul_rn(v.x,v.x));
        s = __fadd_rn(s, __fmul_rn(v.y,v.y));
        s = __fadd_rn(s, __fmul_rn(v.z,v.z));
        s = __fadd_rn(s, __fmul_rn(v.w,v.w));
    }
    g_ssb[code] = s;
}

__global__ __launch_bounds__(BT, 2) void vq_main(const float* __restrict__ x,
                                                 const float* __restrict__ w,
                                                 float* __restrict__ out)
{
    extern __shared__ char sm[];
    float*  ssv  = reinterpret_cast<float*>(sm + SM_SS);
    float*  c4v  = reinterpret_cast<float*>(sm + SM_C4);
    float*  resV = reinterpret_cast<float*>(sm + SM_RV);
    int*    resI = reinterpret_cast<int*>(sm + SM_RI);
    double* sred = reinterpret_cast<double*>(sm + SM_RED);
    const ulonglong2* XS = reinterpret_cast<const ulonglong2*>(sm + SM_X);
    const ulonglong2* CS = reinterpret_cast<const ulonglong2*>(sm + SM_C);

    const int tid = threadIdx.x;
    const int j   = tid & 7;           // code group 0..7
    const int i   = tid >> 3;          // row group 0..31
    const size_t base = (size_t)blockIdx.x * RWS;

    const uint32_t smb = (uint32_t)__cvta_generic_to_shared(sm);
    const uint32_t smx = smb + SM_X;
    const uint32_t smc = smb + SM_C;

    // ---- async x tile: 2048 chunks; m -> (r=m&127, g=m>>7); dst [g][r][16B] ----
    {
        const char* xs = (const char*)x + base*DIM*4;
        #pragma unroll
        for (int q=0;q<8;q++){
            int m = tid + q*BT;
            int r = m & 127, g = m >> 7;
            cp16(smx + (uint32_t)(g*2048 + r*16), xs + (size_t)r*256 + g*16);
        }
        asm volatile("cp.async.commit_group;");
    }
    // ---- async code tile 0 ----
    #pragma unroll
    for (int q=0;q<4;q++){
        int m = tid + q*BT;
        int c = m & 63, g = m >> 6;
        cp16(smc + (uint32_t)(g*1024 + c*16), (const char*)w + (size_t)c*256 + g*16);
    }
    asm volatile("cp.async.commit_group;");

    // ---- norms to smem ----
    #pragma unroll
    for (int k=0;k<KC/BT;k++) ssv[tid + k*BT] = g_ssb[tid + k*BT];
    if (tid < RWS){
        const float4* xr = reinterpret_cast<const float4*>(x + (base + tid)*DIM);
        float s = 0.f;
        #pragma unroll
        for (int q=0;q<16;q++){
            float4 v = xr[q];
            s = __fadd_rn(s, __fmul_rn(v.x,v.x));
            s = __fadd_rn(s, __fmul_rn(v.y,v.y));
            s = __fadd_rn(s, __fmul_rn(v.z,v.z));
            s = __fadd_rn(s, __fmul_rn(v.w,v.w));
        }
        c4v[tid] = s;
    }

    float minv[4] = {3.4e38f,3.4e38f,3.4e38f,3.4e38f};
    int   mini[4] = {0,0,0,0};
    float c4r[4];
    bool c4ld = false;

    #pragma unroll 1
    for (int t=0; t<NTL; t++){
        if (t+1 < NTL){
            const char* srcb = (const char*)w + (size_t)(t+1)*TB;
            uint32_t dstb = smc + (uint32_t)(((t+1)&1)*TB);
            #pragma unroll
            for (int q=0;q<4;q++){
                int m = tid + q*BT;
                int c = m & 63, g = m >> 6;
                cp16(dstb + (uint32_t)(g*1024 + c*16), srcb + (size_t)c*256 + g*16);
            }
            asm volatile("cp.async.commit_group;");
            asm volatile("cp.async.wait_group 1;");
        } else {
            asm volatile("cp.async.wait_group 0;");
        }
        __syncthreads();
        if (!c4ld){
            c4ld = true;
            #pragma unroll
            for (int s=0;s<4;s++) c4r[s] = c4v[i + 32*s];
        }

        const ulonglong2* Ct = CS + (t&1)*(TB/16);
        unsigned long long acc[32];
        #pragma unroll
        for (int q=0;q<32;q++) acc[q] = 0ull;

        #pragma unroll 2
        for (int p=0;p<16;p++){                 // k2-pair: dims 4p..4p+3
            ulonglong2 rA[4], cA[8];
            #pragma unroll
            for (int s=0;s<4;s++) rA[s] = XS[p*128 + i + 32*s];
            #pragma unroll
            for (int r=0;r<8;r++) cA[r] = Ct[p*64 + j + 8*r];
            #pragma unroll
            for (int s=0;s<4;s++){
                #pragma unroll
                for (int r=0;r<8;r++){
                    acc[s*8+r] = ffma2(rA[s].x, cA[r].x, acc[s*8+r]);
                    acc[s*8+r] = ffma2(rA[s].y, cA[r].y, acc[s*8+r]);
                }
            }
        }

        // tail: 32 dots; codes ascend in r for first-min semantics
        float ssq[8];
        #pragma unroll
        for (int r=0;r<8;r++) ssq[r] = ssv[t*CKT + 8*r + j];
        #pragma unroll
        for (int s=0;s<4;s++){
            #pragma unroll
            for (int r=0;r<8;r++){
                float lo, hi;
                unpack2(acc[s*8+r], lo, hi);
                float m  = __fadd_rn(lo, hi);
                float dv = __fmaf_rn(m, -2.0f, __fadd_rn(c4r[s], ssq[r]));
                int  idx = t*CKT + 8*r + j;
                if (dv < minv[s]){ minv[s] = dv; mini[s] = idx; }
            }
        }
        __syncthreads();
    }

    // ---- cross-j reduce (8-lane groups), lexicographic (dv, idx) ----
    #pragma unroll
    for (int off=1; off<8; off<<=1){
        #pragma unroll
        for (int s=0;s<4;s++){
            float od = __shfl_xor_sync(0xffffffffu, minv[s], off);
            int   oi = __shfl_xor_sync(0xffffffffu, mini[s], off);
            if (od < minv[s] || (od == minv[s] && oi < mini[s])){
                minv[s] = od; mini[s] = oi;
            }
        }
    }
    if (j == 0){
        #pragma unroll
        for (int s=0;s<4;s++){ resV[i + 32*s] = minv[s]; resI[i + 32*s] = mini[s]; }
    }
    __syncthreads();

    // ---- loss partial (rows 0..127 by first 128 threads) ----
    if (tid < RWS){
        double v = (double)resV[tid];
        #pragma unroll
        for (int o=16;o>0;o>>=1) v += __shfl_down_sync(0xffffffffu, v, o);
        if ((tid & 31) == 0) sred[tid>>5] = v;
    }
    __syncthreads();
    if (tid == 0){
        atomicAdd(&g_loss_acc, sred[0] + sred[1] + sred[2] + sred[3]);
        __threadfence();
        int done = atomicAdd(&g_ctr, 1);
        if (done == (int)gridDim.x - 1){
            double tot = atomicAdd(&g_loss_acc, 0.0);
            out[0] = (float)(tot*1.25/(double)QELEMS);
            g_ctr = 0;
            g_loss_acc = 0.0;
        }
    }

    // ---- epilogue: indices + straight-through rows (2 threads/row, 32B each) ----
    {
        int rloc = tid >> 1;                 // row 0..127
        int c    = tid & 1;                  // 32-dim half
        size_t grow = base + rloc;
        int idx = resI[rloc];
        if (c == 0) out[1 + QELEMS + grow] = (float)idx;

        const float4* qw = reinterpret_cast<const float4*>(w + (size_t)idx*DIM + c*32);
        const float4* xr = reinterpret_cast<const float4*>(x + grow*DIM + c*32);
        float stq[32];
        #pragma unroll
        for (int q=0;q<8;q++){
            float4 qv = qw[q];
            float4 xv = xr[q];
            stq[4*q+0] = __fadd_rn(xv.x, __fsub_rn(qv.x, xv.x));
            stq[4*q+1] = __fadd_rn(xv.y, __fsub_rn(qv.y, xv.y));
            stq[4*q+2] = __fadd_rn(xv.z, __fsub_rn(qv.z, xv.z));
            stq[4*q+3] = __fadd_rn(xv.w, __fsub_rn(qv.w, xv.w));
        }
        // out+1 is 4B-aligned: 3 scalars, 7 float4, 1 scalar per 32-chunk
        float* og = out + 1 + grow*DIM + c*32;
        og[0]=stq[0]; og[1]=stq[1]; og[2]=stq[2];
        float4* ov = reinterpret_cast<float4*>(og + 3);
        #pragma unroll
        for (int q=0;q<7;q++){
            float4 r;
            r.x=stq[3+4*q]; r.y=stq[4+4*q]; r.z=stq[5+4*q]; r.w=stq[6+4*q];
            ov[q] = r;
        }
        og[31]=stq[31];
    }
}

extern "C" void kernel_launch(void* const* d_in, const int* in_sizes, int n_in,
                              void* d_out, int out_size)
{
    const float* x  = (const float*)d_in[0];
    const float* wt = (const float*)d_in[1];
    float* out = (float*)d_out;

    cudaFuncSetAttribute(vq_main, cudaFuncAttributeMaxDynamicSharedMemorySize, SMEMSZ);

    vq_prep<<<KC/BT, BT>>>(wt);
    vq_main<<<NROWS/RWS, BT, SMEMSZ>>>(x, wt, out);
}

// round 15
// speedup vs baseline: 2.5759x; 1.0127x over previous
#include <cuda_runtime.h>
#include <stdint.h>

#define NROWS   (64*2048)
#define DIM     64
#define KC      1024
#define QELEMS  (NROWS*DIM)
#define BT      256
#define RWS     128                // rows per CTA
#define CKT     64                 // codes per tile
#define NTL     (KC/CKT)           // 16 tiles
#define TB      (CKT*DIM*4)        // 16 KB per code tile

// dynamic smem offsets (bytes)
#define SM_X    0                   // x tile [k2p][row][16B]: 32 KB
#define SM_C    32768               // code tiles x2 [k2p][code][16B]: 32 KB
#define SM_SS   65536               // float ssv[1024]
#define SM_C4   69632               // float c4v[128]
#define SM_RV   70144               // float resV[128]
#define SM_RI   70656               // int resI[128]
#define SM_RED  71168               // double sred[4]
#define SMEMSZ  71232

__device__ double g_loss_acc;
__device__ int    g_ctr;
__device__ float  g_ssb[KC];

static __device__ __forceinline__ unsigned long long ffma2(unsigned long long a,
                                                           unsigned long long b,
                                                           unsigned long long c){
    unsigned long long r;
    asm("fma.rn.f32x2 %0, %1, %2, %3;" : "=l"(r) : "l"(a), "l"(b), "l"(c));
    return r;
}
static __device__ __forceinline__ void unpack2(unsigned long long v, float& a, float& b){
    asm("mov.b64 {%0,%1}, %2;" : "=f"(a), "=f"(b) : "l"(v));
}
static __device__ __forceinline__ void cp16(uint32_t dst, const void* src){
    asm volatile("cp.async.cg.shared.global [%0], [%1], 16;" :: "r"(dst), "l"(src));
}

// prep: exact sequential code norms (reference rounding order), once
__global__ void vq_prep(const float* __restrict__ w){
    int code = blockIdx.x*blockDim.x + threadIdx.x;   // 1024 threads
    const float4* wr = reinterpret_cast<const float4*>(w + (size_t)code*DIM);
    float s = 0.f;
    #pragma unroll
    for (int i=0;i<16;i++){
        float4 v = wr[i];
        s = __fadd_rn(s, __fmul_rn(v.x,v.x));
        s = __fadd_rn(s, __fmul_rn(v.y,v.y));
        s = __fadd_rn(s, __fmul_rn(v.z,v.z));
        s = __fadd_rn(s, __fmul_rn(v.w,v.w));
    }
    g_ssb[code] = s;
}

__global__ __launch_bounds__(BT, 2) void vq_main(const float* __restrict__ x,
                                                 const float* __restrict__ w,
                                                 float* __restrict__ out)
{
    extern __shared__ char sm[];
    float*  ssv  = reinterpret_cast<float*>(sm + SM_SS);
    float*  c4v  = reinterpret_cast<float*>(sm + SM_C4);
    float*  resV = reinterpret_cast<float*>(sm + SM_RV);
    int*    resI = reinterpret_cast<int*>(sm + SM_RI);
    double* sred = reinterpret_cast<double*>(sm + SM_RED);
    const ulonglong2* XS = reinterpret_cast<const ulonglong2*>(sm + SM_X);
    const ulonglong2* CS = reinterpret_cast<const ulonglong2*>(sm + SM_C);

    const int tid = threadIdx.x;
    const int j   = tid & 7;           // code group 0..7
    const int i   = tid >> 3;          // row group 0..31
    const size_t base = (size_t)blockIdx.x * RWS;

    const uint32_t smb = (uint32_t)__cvta_generic_to_shared(sm);
    const uint32_t smx = smb + SM_X;
    const uint32_t smc = smb + SM_C;

    // ---- async x tile: 2048 chunks; m -> (r=m&127, g=m>>7); dst [g][r][16B] ----
    {
        const char* xs = (const char*)x + base*DIM*4;
        #pragma unroll
        for (int q=0;q<8;q++){
            int m = tid + q*BT;
            int r = m & 127, g = m >> 7;
            cp16(smx + (uint32_t)(g*2048 + r*16), xs + (size_t)r*256 + g*16);
        }
        asm volatile("cp.async.commit_group;");
    }
    // ---- async code tile 0 ----
    #pragma unroll
    for (int q=0;q<4;q++){
        int m = tid + q*BT;
        int c = m & 63, g = m >> 6;
        cp16(smc + (uint32_t)(g*1024 + c*16), (const char*)w + (size_t)c*256 + g*16);
    }
    asm volatile("cp.async.commit_group;");

    // ---- norms to smem ----
    #pragma unroll
    for (int k=0;k<KC/BT;k++) ssv[tid + k*BT] = g_ssb[tid + k*BT];
    if (tid < RWS){
        const float4* xr = reinterpret_cast<const float4*>(x + (base + tid)*DIM);
        float s = 0.f;
        #pragma unroll
        for (int q=0;q<16;q++){
            float4 v = xr[q];
            s = __fadd_rn(s, __fmul_rn(v.x,v.x));
            s = __fadd_rn(s, __fmul_rn(v.y,v.y));
            s = __fadd_rn(s, __fmul_rn(v.z,v.z));
            s = __fadd_rn(s, __fmul_rn(v.w,v.w));
        }
        c4v[tid] = s;
    }

    float minv[4] = {3.4e38f,3.4e38f,3.4e38f,3.4e38f};
    int   mini[4] = {0,0,0,0};
    float c4r[4];
    bool c4ld = false;

    #pragma unroll 1
    for (int t=0; t<NTL; t++){
        if (t+1 < NTL){
            const char* srcb = (const char*)w + (size_t)(t+1)*TB;
            uint32_t dstb = smc + (uint32_t)(((t+1)&1)*TB);
            #pragma unroll
            for (int q=0;q<4;q++){
                int m = tid + q*BT;
                int c = m & 63, g = m >> 6;
                cp16(dstb + (uint32_t)(g*1024 + c*16), srcb + (size_t)c*256 + g*16);
            }
            asm volatile("cp.async.commit_group;");
            asm volatile("cp.async.wait_group 1;");
        } else {
            asm volatile("cp.async.wait_group 0;");
        }
        __syncthreads();
        if (!c4ld){
            c4ld = true;
            #pragma unroll
            for (int s=0;s<4;s++) c4r[s] = c4v[i + 32*s];
        }

        const ulonglong2* Ct = CS + (t&1)*(TB/16);
        unsigned long long acc[32];
        #pragma unroll
        for (int q=0;q<32;q++) acc[q] = 0ull;

        #pragma unroll 4
        for (int p=0;p<16;p++){                 // k2-pair: dims 4p..4p+3
            // half 1: rA + codes r=0..3  (peak live regs ~96, not ~132)
            ulonglong2 rA[4], cA[4];
            #pragma unroll
            for (int s=0;s<4;s++) rA[s] = XS[p*128 + i + 32*s];
            #pragma unroll
            for (int r=0;r<4;r++) cA[r] = Ct[p*64 + j + 8*r];
            #pragma unroll
            for (int s=0;s<4;s++){
                #pragma unroll
                for (int r=0;r<4;r++){
                    acc[s*8+r] = ffma2(rA[s].x, cA[r].x, acc[s*8+r]);
                    acc[s*8+r] = ffma2(rA[s].y, cA[r].y, acc[s*8+r]);
                }
            }
            // half 2: codes r=4..7 (reuse cA registers)
            #pragma unroll
            for (int r=0;r<4;r++) cA[r] = Ct[p*64 + j + 8*(r+4)];
            #pragma unroll
            for (int s=0;s<4;s++){
                #pragma unroll
                for (int r=0;r<4;r++){
                    acc[s*8+r+4] = ffma2(rA[s].x, cA[r].x, acc[s*8+r+4]);
                    acc[s*8+r+4] = ffma2(rA[s].y, cA[r].y, acc[s*8+r+4]);
                }
            }
        }

        // tail: 32 dots; codes ascend in r for first-min semantics
        float ssq[8];
        #pragma unroll
        for (int r=0;r<8;r++) ssq[r] = ssv[t*CKT + 8*r + j];
        #pragma unroll
        for (int s=0;s<4;s++){
            #pragma unroll
            for (int r=0;r<8;r++){
                float lo, hi;
                unpack2(acc[s*8+r], lo, hi);
                float m  = __fadd_rn(lo, hi);
                float dv = __fmaf_rn(m, -2.0f, __fadd_rn(c4r[s], ssq[r]));
                int  idx = t*CKT + 8*r + j;
                if (dv < minv[s]){ minv[s] = dv; mini[s] = idx; }
            }
        }
        __syncthreads();
    }

    // ---- cross-j reduce (8-lane groups), lexicographic (dv, idx) ----
    #pragma unroll
    for (int off=1; off<8; off<<=1){
        #pragma unroll
        for (int s=0;s<4;s++){
            float od = __shfl_xor_sync(0xffffffffu, minv[s], off);
            int   oi = __shfl_xor_sync(0xffffffffu, mini[s], off);
            if (od < minv[s] || (od == minv[s] && oi < mini[s])){
                minv[s] = od; mini[s] = oi;
            }
        }
    }
    if (j == 0){
        #pragma unroll
        for (int s=0;s<4;s++){ resV[i + 32*s] = minv[s]; resI[i + 32*s] = mini[s]; }
    }
    __syncthreads();

    // ---- loss partial (rows 0..127 by first 128 threads) ----
    if (tid < RWS){
        double v = (double)resV[tid];
        #pragma unroll
        for (int o=16;o>0;o>>=1) v += __shfl_down_sync(0xffffffffu, v, o);
        if ((tid & 31) == 0) sred[tid>>5] = v;
    }
    __syncthreads();
    if (tid == 0){
        atomicAdd(&g_loss_acc, sred[0] + sred[1] + sred[2] + sred[3]);
        __threadfence();
        int done = atomicAdd(&g_ctr, 1);
        if (done == (int)gridDim.x - 1){
            double tot = atomicAdd(&g_loss_acc, 0.0);
            out[0] = (float)(tot*1.25/(double)QELEMS);
            g_ctr = 0;
            g_loss_acc = 0.0;
        }
    }

    // ---- epilogue: indices + straight-through rows (2 threads/row, 32B each) ----
    {
        int rloc = tid >> 1;                 // row 0..127
        int c    = tid & 1;                  // 32-dim half
        size_t grow = base + rloc;
        int idx = resI[rloc];
        if (c == 0) out[1 + QELEMS + grow] = (float)idx;

        const float4* qw = reinterpret_cast<const float4*>(w + (size_t)idx*DIM + c*32);
        const float4* xr = reinterpret_cast<const float4*>(x + grow*DIM + c*32);
        float stq[32];
        #pragma unroll
        for (int q=0;q<8;q++){
            float4 qv = qw[q];
            float4 xv = xr[q];
            stq[4*q+0] = __fadd_rn(xv.x, __fsub_rn(qv.x, xv.x));
            stq[4*q+1] = __fadd_rn(xv.y, __fsub_rn(qv.y, xv.y));
            stq[4*q+2] = __fadd_rn(xv.z, __fsub_rn(qv.z, xv.z));
            stq[4*q+3] = __fadd_rn(xv.w, __fsub_rn(qv.w, xv.w));
        }
        // out+1 is 4B-aligned: 3 scalars, 7 float4, 1 scalar per 32-chunk
        float* og = out + 1 + grow*DIM + c*32;
        og[0]=stq[0]; og[1]=stq[1]; og[2]=stq[2];
        float4* ov = reinterpret_cast<float4*>(og + 3);
        #pragma unroll
        for (int q=0;q<7;q++){
            float4 r;
            r.x=stq[3+4*q]; r.y=stq[4+4*q]; r.z=stq[5+4*q]; r.w=stq[6+4*q];
            ov[q] = r;
        }
        og[31]=stq[31];
    }
}

extern "C" void kernel_launch(void* const* d_in, const int* in_sizes, int n_in,
                              void* d_out, int out_size)
{
    const float* x  = (const float*)d_in[0];
    const float* wt = (const float*)d_in[1];
    float* out = (float*)d_out;

    cudaFuncSetAttribute(vq_main, cudaFuncAttributeMaxDynamicSharedMemorySize, SMEMSZ);

    vq_prep<<<KC/BT, BT>>>(wt);
    vq_main<<<NROWS/RWS, BT, SMEMSZ>>>(x, wt, out);
}